// round 3
// baseline (speedup 1.0000x reference)
#include <cuda_runtime.h>
#include <cstdint>
#include <cstddef>

// ---------------------------------------------------------------------------
// GCN 2-layer forward on GB300.
//   h1 = x @ W1                      (100000x256 @ 256x128)
//   a1 = relu( Ahat @ h1 + b1 )      Ahat = D^-1/2 (A+I) D^-1/2 (CSR by dst)
//   h2 = a1 @ W2                     (100000x128 @ 128x64)
//   out = Ahat @ h2 + b2
// edge_index is int32 (JAX x64 disabled downcasts the requested int64).
// CSR built once per launch (deg -> scan -> fill), reused by both SpMMs.
// ---------------------------------------------------------------------------

#define NNODES 100000
#define NEDGES 1600000
#define NNZ    (NNODES + NEDGES)   // edges + self loops

__device__ int   g_deg[NNODES];
__device__ int   g_fill[NNODES];
__device__ int   g_rowstart[NNODES + 1];
__device__ int   g_bsums[256];
__device__ float g_dinv[NNODES];
__device__ int   g_col[NNZ];
__device__ float g_wgt[NNZ];
__device__ float g_h[(size_t)NNODES * 128];   // GEMM output (both layers)
__device__ float g_a[(size_t)NNODES * 128];   // relu(aggregated h1)

// ---------------------------------------------------------------------------
// CSR construction
// ---------------------------------------------------------------------------

__global__ void k_init_deg(int n) {
    int i = blockIdx.x * blockDim.x + threadIdx.x;
    if (i < n) g_deg[i] = 1;   // self loop
}

__global__ void k_count(const int* __restrict__ dst, int e) {
    int i = blockIdx.x * blockDim.x + threadIdx.x;
    if (i < e) atomicAdd(&g_deg[dst[i]], 1);
}

__global__ void k_dinv(int n) {
    int i = blockIdx.x * blockDim.x + threadIdx.x;
    if (i < n) g_dinv[i] = rsqrtf((float)g_deg[i]);
}

// block-level exclusive scan of g_deg -> g_rowstart, block totals in g_bsums
__global__ void k_scan1(int n) {
    __shared__ int s[1024];
    int gid = blockIdx.x * 1024 + threadIdx.x;
    int v = (gid < n) ? g_deg[gid] : 0;
    s[threadIdx.x] = v;
    __syncthreads();
    for (int off = 1; off < 1024; off <<= 1) {
        int t = (threadIdx.x >= off) ? s[threadIdx.x - off] : 0;
        __syncthreads();
        s[threadIdx.x] += t;
        __syncthreads();
    }
    if (gid < n) g_rowstart[gid] = s[threadIdx.x] - v;  // exclusive
    if (threadIdx.x == 1023) g_bsums[blockIdx.x] = s[1023];
}

__global__ void k_scan2(int nb) {
    int run = 0;
    for (int b = 0; b < nb; b++) { int t = g_bsums[b]; g_bsums[b] = run; run += t; }
    g_bsums[nb] = run;  // grand total
}

__global__ void k_scan3(int n, int nb) {
    int gid = blockIdx.x * blockDim.x + threadIdx.x;
    if (gid < n) g_rowstart[gid] += g_bsums[gid >> 10];
    if (gid == 0) g_rowstart[n] = g_bsums[nb];
}

__global__ void k_fill_self(int n) {
    int i = blockIdx.x * blockDim.x + threadIdx.x;
    if (i < n) {
        int p = g_rowstart[i];
        g_col[p] = i;
        float d = g_dinv[i];
        g_wgt[p] = d * d;
        g_fill[i] = 1;
    }
}

__global__ void k_fill_edges(const int* __restrict__ src,
                             const int* __restrict__ dst, int e) {
    int i = blockIdx.x * blockDim.x + threadIdx.x;
    if (i < e) {
        int s = src[i];
        int d = dst[i];
        int p = g_rowstart[d] + atomicAdd(&g_fill[d], 1);
        g_col[p] = s;
        g_wgt[p] = g_dinv[s] * g_dinv[d];
    }
}

// ---------------------------------------------------------------------------
// fp32 SGEMM: C[M,BN] = A[M,K] @ W[K,BN], full-width BN (no n-blocking).
// BM=128, BK=16, register tile TM x TN, 256 threads.
// A_GLOBAL: read A from g_a (layer 2) instead of the kernel parameter.
// C always goes to g_h.
// ---------------------------------------------------------------------------

template <int BN, int TN, int K, bool A_GLOBAL>
__launch_bounds__(256)
__global__ void k_sgemm(const float* __restrict__ Ain, const float* __restrict__ W,
                        int M) {
    constexpr int BM = 128, BK = 16, TM = 8;
    const float* __restrict__ A = A_GLOBAL ? (const float*)g_a : Ain;
    float* __restrict__ C = g_h;
    __shared__ float As[BK][BM];
    __shared__ float Ws[BK][BN];
    const int tid = threadIdx.x;
    const int tx = tid % (BN / TN);
    const int ty = tid / (BN / TN);
    const int m0 = blockIdx.x * BM;

    float acc[TM][TN];
#pragma unroll
    for (int i = 0; i < TM; i++)
#pragma unroll
        for (int j = 0; j < TN; j++) acc[i][j] = 0.f;

    for (int k0 = 0; k0 < K; k0 += BK) {
#pragma unroll
        for (int i = tid; i < BM * BK / 4; i += 256) {
            int row = i / (BK / 4);
            int kg = i % (BK / 4);
            int gr = m0 + row;
            float4 v = make_float4(0.f, 0.f, 0.f, 0.f);
            if (gr < M) v = *(const float4*)(A + (size_t)gr * K + k0 + kg * 4);
            As[kg * 4 + 0][row] = v.x;
            As[kg * 4 + 1][row] = v.y;
            As[kg * 4 + 2][row] = v.z;
            As[kg * 4 + 3][row] = v.w;
        }
#pragma unroll
        for (int i = tid; i < BK * BN / 4; i += 256) {
            int kk = i / (BN / 4);
            int ng = i % (BN / 4);
            *(float4*)&Ws[kk][ng * 4] =
                *(const float4*)(W + (size_t)(k0 + kk) * BN + ng * 4);
        }
        __syncthreads();

#pragma unroll
        for (int kk = 0; kk < BK; kk++) {
            float af[TM], wf[TN];
#pragma unroll
            for (int i = 0; i < TM; i++) af[i] = As[kk][ty * TM + i];
#pragma unroll
            for (int j = 0; j < TN; j++) wf[j] = Ws[kk][tx * TN + j];
#pragma unroll
            for (int i = 0; i < TM; i++)
#pragma unroll
                for (int j = 0; j < TN; j++) acc[i][j] += af[i] * wf[j];
        }
        __syncthreads();
    }

#pragma unroll
    for (int i = 0; i < TM; i++) {
        int gr = m0 + ty * TM + i;
        if (gr < M) {
#pragma unroll
            for (int j = 0; j < TN; j += 4) {
                *(float4*)(C + (size_t)gr * BN + tx * TN + j) =
                    make_float4(acc[i][j], acc[i][j + 1], acc[i][j + 2], acc[i][j + 3]);
            }
        }
    }
}

// ---------------------------------------------------------------------------
// SpMM gather: out[n,:] = (opt relu)( sum_e wgt[e]*h[col[e],:] + bias )
// one warp per node, lane covers F/32 contiguous features.
// h always read from g_h. OUT_PARAM: write kernel-param out (final layer),
// else write g_a.
// ---------------------------------------------------------------------------

template <int F, bool RELU, bool OUT_PARAM>
__launch_bounds__(256)
__global__ void k_spmm(const float* __restrict__ bias, float* __restrict__ outp,
                       int n) {
    const float* __restrict__ h = g_h;
    float* __restrict__ out = OUT_PARAM ? outp : (float*)g_a;
    int w = (blockIdx.x * 256 + threadIdx.x) >> 5;
    int lane = threadIdx.x & 31;
    if (w >= n) return;
    int beg = g_rowstart[w], end = g_rowstart[w + 1];

    if (F == 128) {
        float4 acc = make_float4(0.f, 0.f, 0.f, 0.f);
        const float* hb = h + lane * 4;
        for (int e = beg; e < end; e++) {
            int s = g_col[e];
            float wt = g_wgt[e];
            float4 v = *(const float4*)(hb + (size_t)s * 128);
            acc.x += wt * v.x; acc.y += wt * v.y;
            acc.z += wt * v.z; acc.w += wt * v.w;
        }
        float4 b = *(const float4*)(bias + lane * 4);
        acc.x += b.x; acc.y += b.y; acc.z += b.z; acc.w += b.w;
        if (RELU) {
            acc.x = fmaxf(acc.x, 0.f); acc.y = fmaxf(acc.y, 0.f);
            acc.z = fmaxf(acc.z, 0.f); acc.w = fmaxf(acc.w, 0.f);
        }
        *(float4*)(out + (size_t)w * 128 + lane * 4) = acc;
    } else {  // F == 64
        float2 acc = make_float2(0.f, 0.f);
        const float* hb = h + lane * 2;
        for (int e = beg; e < end; e++) {
            int s = g_col[e];
            float wt = g_wgt[e];
            float2 v = *(const float2*)(hb + (size_t)s * 64);
            acc.x += wt * v.x; acc.y += wt * v.y;
        }
        float2 b = *(const float2*)(bias + lane * 2);
        acc.x += b.x; acc.y += b.y;
        if (RELU) { acc.x = fmaxf(acc.x, 0.f); acc.y = fmaxf(acc.y, 0.f); }
        *(float2*)(out + (size_t)w * 64 + lane * 2) = acc;
    }
}

// ---------------------------------------------------------------------------

extern "C" void kernel_launch(void* const* d_in, const int* in_sizes, int n_in,
                              void* d_out, int out_size) {
    const float* x = (const float*)d_in[0];
    const int* ei = (const int*)d_in[1];      // int32! (JAX x64 disabled)
    const float* W1 = (const float*)d_in[2];
    const float* b1 = (const float*)d_in[3];
    const float* W2 = (const float*)d_in[4];
    const float* b2 = (const float*)d_in[5];
    float* out = (float*)d_out;

    const int N = in_sizes[0] / 256;   // 100000
    const int E = in_sizes[1] / 2;     // 1600000
    const int* src = ei;
    const int* dst = ei + E;
    const int NB = (N + 1023) / 1024;

    // CSR build
    k_init_deg<<<(N + 255) / 256, 256>>>(N);
    k_count<<<(E + 255) / 256, 256>>>(dst, E);
    k_dinv<<<(N + 255) / 256, 256>>>(N);
    k_scan1<<<NB, 1024>>>(N);
    k_scan2<<<1, 1>>>(NB);
    k_scan3<<<(N + 255) / 256, 256>>>(N, NB);
    k_fill_self<<<(N + 255) / 256, 256>>>(N);
    k_fill_edges<<<(E + 255) / 256, 256>>>(src, dst, E);

    // layer 1: g_h = x@W1 ; g_a = relu(Ahat g_h + b1)
    k_sgemm<128, 8, 256, false><<<(N + 127) / 128, 256>>>(x, W1, N);
    {
        int blocks = ((N * 32) + 255) / 256;
        k_spmm<128, true, false><<<blocks, 256>>>(b1, nullptr, N);
    }

    // layer 2: g_h = g_a@W2 ; out = Ahat g_h + b2
    k_sgemm<64, 4, 128, true><<<(N + 127) / 128, 256>>>(nullptr, W2, N);
    {
        int blocks = ((N * 32) + 255) / 256;
        k_spmm<64, false, true><<<blocks, 256>>>(b2, out, N);
    }
}

// round 4
// speedup vs baseline: 1.0214x; 1.0214x over previous
#include <cuda_runtime.h>
#include <cstdint>
#include <cstddef>

// ---------------------------------------------------------------------------
// GCN 2-layer forward on GB300.
//   h1 = x @ W1                      (100000x256 @ 256x128)
//   a1 = relu( Ahat @ h1 + b1 )      Ahat = D^-1/2 (A+I) D^-1/2 (CSR by dst)
//   h2 = a1 @ W2                     (100000x128 @ 128x64)
//   out = Ahat @ h2 + b2
// edge_index is int32. CSR built per launch, reused by both SpMMs.
// GEMM inner loop uses packed fma.rn.f32x2 (Blackwell FFMA2, 2x fp32/issue).
// ---------------------------------------------------------------------------

#define NNODES 100000
#define NEDGES 1600000
#define NNZ    (NNODES + NEDGES)   // edges + self loops

__device__ int   g_deg[NNODES];
__device__ int   g_fill[NNODES];
__device__ int   g_rowstart[NNODES + 1];
__device__ int   g_bsums[256];
__device__ float g_dinv[NNODES];
__device__ int   g_col[NNZ];
__device__ float g_wgt[NNZ];
__device__ float g_h[(size_t)NNODES * 128];   // GEMM output (both layers)
__device__ float g_a[(size_t)NNODES * 128];   // relu(aggregated h1)

// ---------------------------------------------------------------------------
// CSR construction
// ---------------------------------------------------------------------------

__global__ void k_init_deg(int n) {
    int i = blockIdx.x * blockDim.x + threadIdx.x;
    if (i < n) g_deg[i] = 1;   // self loop
}

__global__ void k_count(const int* __restrict__ dst, int e) {
    int i = blockIdx.x * blockDim.x + threadIdx.x;
    if (i < e) atomicAdd(&g_deg[dst[i]], 1);
}

// block-level exclusive scan of g_deg -> g_rowstart, block totals in g_bsums
__global__ void k_scan1(int n) {
    __shared__ int s[1024];
    int gid = blockIdx.x * 1024 + threadIdx.x;
    int v = (gid < n) ? g_deg[gid] : 0;
    s[threadIdx.x] = v;
    __syncthreads();
    for (int off = 1; off < 1024; off <<= 1) {
        int t = (threadIdx.x >= off) ? s[threadIdx.x - off] : 0;
        __syncthreads();
        s[threadIdx.x] += t;
        __syncthreads();
    }
    if (gid < n) g_rowstart[gid] = s[threadIdx.x] - v;  // exclusive
    if (threadIdx.x == 1023) g_bsums[blockIdx.x] = s[1023];
}

__global__ void k_scan2(int nb) {
    int run = 0;
    for (int b = 0; b < nb; b++) { int t = g_bsums[b]; g_bsums[b] = run; run += t; }
    g_bsums[nb] = run;  // grand total
}

__global__ void k_scan3(int n, int nb) {
    int gid = blockIdx.x * blockDim.x + threadIdx.x;
    if (gid < n) g_rowstart[gid] += g_bsums[gid >> 10];
    if (gid == 0) g_rowstart[n] = g_bsums[nb];
}

// dinv + self-loop entry (dinv fused here; runs before fill_edges)
__global__ void k_fill_self(int n) {
    int i = blockIdx.x * blockDim.x + threadIdx.x;
    if (i < n) {
        float d = rsqrtf((float)g_deg[i]);
        g_dinv[i] = d;
        int p = g_rowstart[i];
        g_col[p] = i;
        g_wgt[p] = d * d;
        g_fill[i] = 1;
    }
}

__global__ void k_fill_edges(const int* __restrict__ src,
                             const int* __restrict__ dst, int e) {
    int i = blockIdx.x * blockDim.x + threadIdx.x;
    if (i < e) {
        int s = src[i];
        int d = dst[i];
        int p = g_rowstart[d] + atomicAdd(&g_fill[d], 1);
        g_col[p] = s;
        g_wgt[p] = g_dinv[s] * g_dinv[d];
    }
}

// ---------------------------------------------------------------------------
// fp32 SGEMM with packed f32x2 FMA.
// C[M,BN] = A[M,K] @ W[K,BN].  BM=128, BK=16, per-thread tile TM=8 x TN.
// Accumulator packed along m: acc2[i2][j] holds rows (2*i2, 2*i2+1), col j.
// A pairs loaded directly as 64-bit from smem (m-contiguous); W broadcast
// packed via mov.b64 {w,w} (alu pipe, hidden under fma pipe).
// ---------------------------------------------------------------------------

__device__ __forceinline__ unsigned long long pack_dup(float w) {
    unsigned long long r;
    asm("mov.b64 %0, {%1, %2};" : "=l"(r) : "f"(w), "f"(w));
    return r;
}

__device__ __forceinline__ void ffma2(unsigned long long& d,
                                      unsigned long long a,
                                      unsigned long long b) {
    asm("fma.rn.f32x2 %0, %1, %2, %0;" : "+l"(d) : "l"(a), "l"(b));
}

template <int BN, int TN, int K, bool A_GLOBAL>
__launch_bounds__(256)
__global__ void k_sgemm(const float* __restrict__ Ain, const float* __restrict__ W,
                        int M) {
    constexpr int BM = 128, BK = 16, TM = 8;
    const float* __restrict__ A = A_GLOBAL ? (const float*)g_a : Ain;
    float* __restrict__ C = g_h;
    __shared__ __align__(16) float As[BK][BM];
    __shared__ __align__(16) float Ws[BK][BN];
    const int tid = threadIdx.x;
    const int tx = tid % (BN / TN);
    const int ty = tid / (BN / TN);
    const int m0 = blockIdx.x * BM;

    unsigned long long acc2[TM / 2][TN];
#pragma unroll
    for (int i = 0; i < TM / 2; i++)
#pragma unroll
        for (int j = 0; j < TN; j++) acc2[i][j] = 0ull;

    for (int k0 = 0; k0 < K; k0 += BK) {
#pragma unroll
        for (int i = tid; i < BM * BK / 4; i += 256) {
            int row = i / (BK / 4);
            int kg = i % (BK / 4);
            int gr = m0 + row;
            float4 v = make_float4(0.f, 0.f, 0.f, 0.f);
            if (gr < M) v = *(const float4*)(A + (size_t)gr * K + k0 + kg * 4);
            As[kg * 4 + 0][row] = v.x;
            As[kg * 4 + 1][row] = v.y;
            As[kg * 4 + 2][row] = v.z;
            As[kg * 4 + 3][row] = v.w;
        }
#pragma unroll
        for (int i = tid; i < BK * BN / 4; i += 256) {
            int kk = i / (BN / 4);
            int ng = i % (BN / 4);
            *(float4*)&Ws[kk][ng * 4] =
                *(const float4*)(W + (size_t)(k0 + kk) * BN + ng * 4);
        }
        __syncthreads();

#pragma unroll
        for (int kk = 0; kk < BK; kk++) {
            unsigned long long af2[TM / 2];
#pragma unroll
            for (int i = 0; i < TM / 2; i++)
                af2[i] = *(const unsigned long long*)&As[kk][ty * TM + i * 2];
            float wf[TN];
#pragma unroll
            for (int j = 0; j < TN; j += 4)
                *(float4*)&wf[j] = *(const float4*)&Ws[kk][tx * TN + j];
            unsigned long long wf2[TN];
#pragma unroll
            for (int j = 0; j < TN; j++) wf2[j] = pack_dup(wf[j]);
#pragma unroll
            for (int i = 0; i < TM / 2; i++)
#pragma unroll
                for (int j = 0; j < TN; j++) ffma2(acc2[i][j], af2[i], wf2[j]);
        }
        __syncthreads();
    }

    // epilogue: unpack pairs (rows 2*i2, 2*i2+1)
#pragma unroll
    for (int i = 0; i < TM / 2; i++) {
        float lo[TN], hi[TN];
#pragma unroll
        for (int j = 0; j < TN; j++) {
            asm("mov.b64 {%0, %1}, %2;" : "=f"(lo[j]), "=f"(hi[j]) : "l"(acc2[i][j]));
        }
        int gr0 = m0 + ty * TM + i * 2;
        if (gr0 < M) {
#pragma unroll
            for (int j = 0; j < TN; j += 4)
                *(float4*)(C + (size_t)gr0 * BN + tx * TN + j) =
                    make_float4(lo[j], lo[j + 1], lo[j + 2], lo[j + 3]);
        }
        if (gr0 + 1 < M) {
#pragma unroll
            for (int j = 0; j < TN; j += 4)
                *(float4*)(C + (size_t)(gr0 + 1) * BN + tx * TN + j) =
                    make_float4(hi[j], hi[j + 1], hi[j + 2], hi[j + 3]);
        }
    }
}

// ---------------------------------------------------------------------------
// SpMM gather: out[n,:] = (opt relu)( sum_e wgt[e]*h[col[e],:] + bias )
// one warp per node, lane covers F/32 contiguous features.
// ---------------------------------------------------------------------------

template <int F, bool RELU, bool OUT_PARAM>
__launch_bounds__(256)
__global__ void k_spmm(const float* __restrict__ bias, float* __restrict__ outp,
                       int n) {
    const float* __restrict__ h = g_h;
    float* __restrict__ out = OUT_PARAM ? outp : (float*)g_a;
    int w = (blockIdx.x * 256 + threadIdx.x) >> 5;
    int lane = threadIdx.x & 31;
    if (w >= n) return;
    int beg = g_rowstart[w], end = g_rowstart[w + 1];

    if (F == 128) {
        float4 acc = make_float4(0.f, 0.f, 0.f, 0.f);
        const float* hb = h + lane * 4;
        for (int e = beg; e < end; e++) {
            int s = g_col[e];
            float wt = g_wgt[e];
            float4 v = *(const float4*)(hb + (size_t)s * 128);
            acc.x += wt * v.x; acc.y += wt * v.y;
            acc.z += wt * v.z; acc.w += wt * v.w;
        }
        float4 b = *(const float4*)(bias + lane * 4);
        acc.x += b.x; acc.y += b.y; acc.z += b.z; acc.w += b.w;
        if (RELU) {
            acc.x = fmaxf(acc.x, 0.f); acc.y = fmaxf(acc.y, 0.f);
            acc.z = fmaxf(acc.z, 0.f); acc.w = fmaxf(acc.w, 0.f);
        }
        *(float4*)(out + (size_t)w * 128 + lane * 4) = acc;
    } else {  // F == 64
        float2 acc = make_float2(0.f, 0.f);
        const float* hb = h + lane * 2;
        for (int e = beg; e < end; e++) {
            int s = g_col[e];
            float wt = g_wgt[e];
            float2 v = *(const float2*)(hb + (size_t)s * 64);
            acc.x += wt * v.x; acc.y += wt * v.y;
        }
        float2 b = *(const float2*)(bias + lane * 2);
        acc.x += b.x; acc.y += b.y;
        if (RELU) { acc.x = fmaxf(acc.x, 0.f); acc.y = fmaxf(acc.y, 0.f); }
        *(float2*)(out + (size_t)w * 64 + lane * 2) = acc;
    }
}

// ---------------------------------------------------------------------------

extern "C" void kernel_launch(void* const* d_in, const int* in_sizes, int n_in,
                              void* d_out, int out_size) {
    const float* x = (const float*)d_in[0];
    const int* ei = (const int*)d_in[1];      // int32 (JAX x64 disabled)
    const float* W1 = (const float*)d_in[2];
    const float* b1 = (const float*)d_in[3];
    const float* W2 = (const float*)d_in[4];
    const float* b2 = (const float*)d_in[5];
    float* out = (float*)d_out;

    const int N = in_sizes[0] / 256;   // 100000
    const int E = in_sizes[1] / 2;     // 1600000
    const int* src = ei;
    const int* dst = ei + E;
    const int NB = (N + 1023) / 1024;

    // CSR build
    k_init_deg<<<(N + 255) / 256, 256>>>(N);
    k_count<<<(E + 255) / 256, 256>>>(dst, E);
    k_scan1<<<NB, 1024>>>(N);
    k_scan2<<<1, 1>>>(NB);
    k_scan3<<<(N + 255) / 256, 256>>>(N, NB);
    k_fill_self<<<(N + 255) / 256, 256>>>(N);
    k_fill_edges<<<(E + 255) / 256, 256>>>(src, dst, E);

    // layer 1: g_h = x@W1 ; g_a = relu(Ahat g_h + b1)
    k_sgemm<128, 8, 256, false><<<(N + 127) / 128, 256>>>(x, W1, N);
    {
        int blocks = ((N * 32) + 255) / 256;
        k_spmm<128, true, false><<<blocks, 256>>>(b1, nullptr, N);
    }

    // layer 2: g_h = g_a@W2 ; out = Ahat g_h + b2
    k_sgemm<64, 4, 128, true><<<(N + 127) / 128, 256>>>(nullptr, W2, N);
    {
        int blocks = ((N * 32) + 255) / 256;
        k_spmm<64, false, true><<<blocks, 256>>>(b2, out, N);
    }
}

// round 5
// speedup vs baseline: 1.0871x; 1.0643x over previous
#include <cuda_runtime.h>
#include <cuda_bf16.h>
#include <cstdint>
#include <cstddef>

// ---------------------------------------------------------------------------
// GCN 2-layer forward on GB300.
//   h1 = x @ W1   (bf16-stored)      (100000x256 @ 256x128)
//   a1 = relu( Ahat @ h1 + b1 )      Ahat = D^-1/2 (A+I) D^-1/2 (CSR by dst)
//   h2 = a1 @ W2  (fp32)             (100000x128 @ 128x64)
//   out = Ahat @ h2 + b2
// Launch order puts sgemm1 4th so ncu (-s 5 -c 1, lands on launch #4)
// profiles the GEMM. h1 stored bf16 to halve the L2-bound SpMM1 gather.
// ---------------------------------------------------------------------------

#define NNODES 100000
#define NEDGES 1600000
#define NNZ    (NNODES + NEDGES)   // edges + self loops

__device__ int   g_deg[NNODES];
__device__ int   g_fill[NNODES];
__device__ int   g_rowstart[NNODES + 1];
__device__ int   g_bsums[256];
__device__ float g_dinv[NNODES];
__device__ int   g_col[NNZ];
__device__ float g_wgt[NNZ];
__device__ __nv_bfloat16 g_hb[(size_t)NNODES * 128];  // h1 (bf16)
__device__ float g_h[(size_t)NNODES * 64];            // h2 (fp32)
__device__ float g_a[(size_t)NNODES * 128];           // a1 = relu(agg h1)

// ---------------------------------------------------------------------------
// CSR construction
// ---------------------------------------------------------------------------

__global__ void k_init_deg(int n) {
    int i = blockIdx.x * blockDim.x + threadIdx.x;
    if (i < n) g_deg[i] = 1;   // self loop
}

__global__ void k_count(const int* __restrict__ dst, int e) {
    int i = blockIdx.x * blockDim.x + threadIdx.x;
    if (i < e) atomicAdd(&g_deg[dst[i]], 1);
}

// block-level exclusive scan of g_deg -> g_rowstart, block totals in g_bsums
__global__ void k_scan1(int n) {
    __shared__ int s[1024];
    int gid = blockIdx.x * 1024 + threadIdx.x;
    int v = (gid < n) ? g_deg[gid] : 0;
    s[threadIdx.x] = v;
    __syncthreads();
    for (int off = 1; off < 1024; off <<= 1) {
        int t = (threadIdx.x >= off) ? s[threadIdx.x - off] : 0;
        __syncthreads();
        s[threadIdx.x] += t;
        __syncthreads();
    }
    if (gid < n) g_rowstart[gid] = s[threadIdx.x] - v;  // exclusive
    if (threadIdx.x == 1023) g_bsums[blockIdx.x] = s[1023];
}

// fused: block-prefix add + dinv + self-loop fill + rowstart[n]
__global__ void k_scanfill(int n, int nb) {
    __shared__ int soff;
    int gid = blockIdx.x * 1024 + threadIdx.x;
    if (threadIdx.x == 0) {
        int o = 0;
        for (int b = 0; b < (int)blockIdx.x; b++) o += g_bsums[b];
        soff = o;
    }
    __syncthreads();
    if (gid < n) {
        int rs = g_rowstart[gid] + soff;
        g_rowstart[gid] = rs;
        float d = rsqrtf((float)g_deg[gid]);
        g_dinv[gid] = d;
        g_col[rs] = gid;
        g_wgt[rs] = d * d;
        g_fill[gid] = 1;
    }
    if (gid == 0) {
        int o = 0;
        for (int b = 0; b < nb; b++) o += g_bsums[b];
        g_rowstart[n] = o;
    }
}

__global__ void k_fill_edges(const int* __restrict__ src,
                             const int* __restrict__ dst, int e) {
    int i = blockIdx.x * blockDim.x + threadIdx.x;
    if (i < e) {
        int s = src[i];
        int d = dst[i];
        int p = g_rowstart[d] + atomicAdd(&g_fill[d], 1);
        g_col[p] = s;
        g_wgt[p] = g_dinv[s] * g_dinv[d];
    }
}

// ---------------------------------------------------------------------------
// fp32 SGEMM with packed f32x2 FMA.  C = A[M,K] @ W[K,BN].
// BM=128, BK=16, per-thread tile TM=8 x TN, 256 threads.
// C_BF16: convert output to bf16 and write g_hb; else fp32 to g_h.
// ---------------------------------------------------------------------------

__device__ __forceinline__ unsigned long long pack_dup(float w) {
    unsigned long long r;
    asm("mov.b64 %0, {%1, %2};" : "=l"(r) : "f"(w), "f"(w));
    return r;
}

__device__ __forceinline__ void ffma2(unsigned long long& d,
                                      unsigned long long a,
                                      unsigned long long b) {
    asm("fma.rn.f32x2 %0, %1, %2, %0;" : "+l"(d) : "l"(a), "l"(b));
}

template <int BN, int TN, int K, bool A_GLOBAL, bool C_BF16>
__launch_bounds__(256)
__global__ void k_sgemm(const float* __restrict__ Ain, const float* __restrict__ W,
                        int M) {
    constexpr int BM = 128, BK = 16, TM = 8;
    const float* __restrict__ A = A_GLOBAL ? (const float*)g_a : Ain;
    __shared__ __align__(16) float As[BK][BM];
    __shared__ __align__(16) float Ws[BK][BN];
    const int tid = threadIdx.x;
    const int tx = tid % (BN / TN);
    const int ty = tid / (BN / TN);
    const int m0 = blockIdx.x * BM;

    unsigned long long acc2[TM / 2][TN];
#pragma unroll
    for (int i = 0; i < TM / 2; i++)
#pragma unroll
        for (int j = 0; j < TN; j++) acc2[i][j] = 0ull;

    for (int k0 = 0; k0 < K; k0 += BK) {
#pragma unroll
        for (int i = tid; i < BM * BK / 4; i += 256) {
            int row = i / (BK / 4);
            int kg = i % (BK / 4);
            int gr = m0 + row;
            float4 v = make_float4(0.f, 0.f, 0.f, 0.f);
            if (gr < M) v = *(const float4*)(A + (size_t)gr * K + k0 + kg * 4);
            As[kg * 4 + 0][row] = v.x;
            As[kg * 4 + 1][row] = v.y;
            As[kg * 4 + 2][row] = v.z;
            As[kg * 4 + 3][row] = v.w;
        }
#pragma unroll
        for (int i = tid; i < BK * BN / 4; i += 256) {
            int kk = i / (BN / 4);
            int ng = i % (BN / 4);
            *(float4*)&Ws[kk][ng * 4] =
                *(const float4*)(W + (size_t)(k0 + kk) * BN + ng * 4);
        }
        __syncthreads();

#pragma unroll
        for (int kk = 0; kk < BK; kk++) {
            unsigned long long af2[TM / 2];
#pragma unroll
            for (int i = 0; i < TM / 2; i++)
                af2[i] = *(const unsigned long long*)&As[kk][ty * TM + i * 2];
            float wf[TN];
#pragma unroll
            for (int j = 0; j < TN; j += 4)
                *(float4*)&wf[j] = *(const float4*)&Ws[kk][tx * TN + j];
            unsigned long long wf2[TN];
#pragma unroll
            for (int j = 0; j < TN; j++) wf2[j] = pack_dup(wf[j]);
#pragma unroll
            for (int i = 0; i < TM / 2; i++)
#pragma unroll
                for (int j = 0; j < TN; j++) ffma2(acc2[i][j], af2[i], wf2[j]);
        }
        __syncthreads();
    }

    // epilogue: unpack row pairs, store fp32 or bf16
#pragma unroll
    for (int i = 0; i < TM / 2; i++) {
        float lo[TN], hi[TN];
#pragma unroll
        for (int j = 0; j < TN; j++) {
            asm("mov.b64 {%0, %1}, %2;" : "=f"(lo[j]), "=f"(hi[j]) : "l"(acc2[i][j]));
        }
        int gr0 = m0 + ty * TM + i * 2;
        if (C_BF16) {
            __nv_bfloat16* Cb = g_hb;
            if (gr0 < M) {
                __nv_bfloat162 o[TN / 2];
#pragma unroll
                for (int j = 0; j < TN / 2; j++)
                    o[j] = __floats2bfloat162_rn(lo[2 * j], lo[2 * j + 1]);
                *(uint4*)(Cb + (size_t)gr0 * BN + tx * TN) = *(uint4*)o;
            }
            if (gr0 + 1 < M) {
                __nv_bfloat162 o[TN / 2];
#pragma unroll
                for (int j = 0; j < TN / 2; j++)
                    o[j] = __floats2bfloat162_rn(hi[2 * j], hi[2 * j + 1]);
                *(uint4*)(Cb + (size_t)(gr0 + 1) * BN + tx * TN) = *(uint4*)o;
            }
        } else {
            float* C = g_h;
            if (gr0 < M) {
#pragma unroll
                for (int j = 0; j < TN; j += 4)
                    *(float4*)(C + (size_t)gr0 * BN + tx * TN + j) =
                        make_float4(lo[j], lo[j + 1], lo[j + 2], lo[j + 3]);
            }
            if (gr0 + 1 < M) {
#pragma unroll
                for (int j = 0; j < TN; j += 4)
                    *(float4*)(C + (size_t)(gr0 + 1) * BN + tx * TN + j) =
                        make_float4(hi[j], hi[j + 1], hi[j + 2], hi[j + 3]);
            }
        }
    }
}

// ---------------------------------------------------------------------------
// SpMM layer 1: a1 = relu( Ahat @ h1(bf16) + b1 ), F=128.
// one warp per node; lane covers 4 features (8B bf16 per edge per lane).
// ---------------------------------------------------------------------------

__launch_bounds__(256)
__global__ void k_spmm1(const float* __restrict__ bias, int n) {
    int w = (blockIdx.x * 256 + threadIdx.x) >> 5;
    int lane = threadIdx.x & 31;
    if (w >= n) return;
    int beg = g_rowstart[w], end = g_rowstart[w + 1];

    float4 acc = make_float4(0.f, 0.f, 0.f, 0.f);
    const __nv_bfloat16* hb = g_hb + lane * 4;
    for (int e = beg; e < end; e++) {
        int s = g_col[e];
        float wt = g_wgt[e];
        uint2 raw = *(const uint2*)(hb + (size_t)s * 128);
        __nv_bfloat162 v01 = *reinterpret_cast<__nv_bfloat162*>(&raw.x);
        __nv_bfloat162 v23 = *reinterpret_cast<__nv_bfloat162*>(&raw.y);
        float2 f01 = __bfloat1622float2(v01);
        float2 f23 = __bfloat1622float2(v23);
        acc.x += wt * f01.x; acc.y += wt * f01.y;
        acc.z += wt * f23.x; acc.w += wt * f23.y;
    }
    float4 b = *(const float4*)(bias + lane * 4);
    acc.x = fmaxf(acc.x + b.x, 0.f);
    acc.y = fmaxf(acc.y + b.y, 0.f);
    acc.z = fmaxf(acc.z + b.z, 0.f);
    acc.w = fmaxf(acc.w + b.w, 0.f);
    *(float4*)(g_a + (size_t)w * 128 + lane * 4) = acc;
}

// ---------------------------------------------------------------------------
// SpMM layer 2: out = Ahat @ h2(fp32) + b2, F=64. lane covers 2 features.
// ---------------------------------------------------------------------------

__launch_bounds__(256)
__global__ void k_spmm2(const float* __restrict__ bias, float* __restrict__ out,
                        int n) {
    int w = (blockIdx.x * 256 + threadIdx.x) >> 5;
    int lane = threadIdx.x & 31;
    if (w >= n) return;
    int beg = g_rowstart[w], end = g_rowstart[w + 1];

    float2 acc = make_float2(0.f, 0.f);
    const float* hb = g_h + lane * 2;
    for (int e = beg; e < end; e++) {
        int s = g_col[e];
        float wt = g_wgt[e];
        float2 v = *(const float2*)(hb + (size_t)s * 64);
        acc.x += wt * v.x; acc.y += wt * v.y;
    }
    float2 b = *(const float2*)(bias + lane * 2);
    acc.x += b.x; acc.y += b.y;
    *(float2*)(out + (size_t)w * 64 + lane * 2) = acc;
}

// ---------------------------------------------------------------------------

extern "C" void kernel_launch(void* const* d_in, const int* in_sizes, int n_in,
                              void* d_out, int out_size) {
    const float* x = (const float*)d_in[0];
    const int* ei = (const int*)d_in[1];      // int32 (JAX x64 disabled)
    const float* W1 = (const float*)d_in[2];
    const float* b1 = (const float*)d_in[3];
    const float* W2 = (const float*)d_in[4];
    const float* b2 = (const float*)d_in[5];
    float* out = (float*)d_out;

    const int N = in_sizes[0] / 256;   // 100000
    const int E = in_sizes[1] / 2;     // 1600000
    const int* src = ei;
    const int* dst = ei + E;
    const int NB = (N + 1023) / 1024;

    // #1..#3: CSR phase A
    k_init_deg<<<(N + 255) / 256, 256>>>(N);
    k_count<<<(E + 255) / 256, 256>>>(dst, E);
    k_scan1<<<NB, 1024>>>(N);

    // #4: GEMM1 (independent of CSR fill) — ncu capture lands here
    k_sgemm<128, 8, 256, false, true><<<(N + 127) / 128, 256>>>(x, W1, N);

    // #5..#6: CSR phase B
    k_scanfill<<<NB, 1024>>>(N, NB);
    k_fill_edges<<<(E + 255) / 256, 256>>>(src, dst, E);

    // #7: a1 = relu(Ahat h1 + b1)
    k_spmm1<<<((N * 32) + 255) / 256, 256>>>(b1, N);

    // #8: h2 = a1 @ W2 (fp32)
    k_sgemm<64, 4, 128, true, false><<<(N + 127) / 128, 256>>>(nullptr, W2, N);

    // #9: out = Ahat h2 + b2
    k_spmm2<<<((N * 32) + 255) / 256, 256>>>(b2, out, N);
}

// round 7
// speedup vs baseline: 1.3551x; 1.2465x over previous
#include <cuda_runtime.h>
#include <cuda_bf16.h>
#include <cstdint>
#include <cstddef>

// ---------------------------------------------------------------------------
// GCN 2-layer forward on GB300 — HMMA (mma.sync bf16) GEMMs + gather SpMM.
//   h1 = x @ W1    (3-term bf16 split, bf16-stored)
//   a1 = relu( Ahat @ h1 + b1 )
//   h2 = a1 @ W2   (3-term bf16 split, fp32-stored)
//   out = Ahat @ h2 + b2
// tcgen05 unavailable (harness PTX targets sm_103 without 'a'); use
// mma.sync.aligned.m16n8k16.row.col.f32.bf16.bf16.f32 + ldmatrix instead.
// ---------------------------------------------------------------------------

#define NNODES 100000
#define NEDGES 1600000
#define NNZ    (NNODES + NEDGES)

__device__ int   g_deg[NNODES];
__device__ int   g_fill[NNODES];
__device__ int   g_rowstart[NNODES + 1];
__device__ int   g_bsums[256];
__device__ float g_dinv[NNODES];
__device__ int   g_col[NNZ];
__device__ float g_wgt[NNZ];
__device__ __nv_bfloat16 g_hb[(size_t)NNODES * 128];  // h1 (bf16)
__device__ float g_h[(size_t)NNODES * 64];            // h2 (fp32)
__device__ float g_a[(size_t)NNODES * 128];           // a1
// W split (transposed, K-major rows): [N][K] bf16 hi/lo
__device__ __nv_bfloat16 g_w1h[128 * 256];
__device__ __nv_bfloat16 g_w1l[128 * 256];
__device__ __nv_bfloat16 g_w2h[64 * 128];
__device__ __nv_bfloat16 g_w2l[64 * 128];

// ------------------------------ helpers ------------------------------------

__device__ __forceinline__ uint32_t smem_u32(const void* p) {
    uint32_t a;
    asm("{ .reg .u64 t; cvta.to.shared.u64 t, %1; cvt.u32.u64 %0, t; }"
        : "=r"(a) : "l"(p));
    return a;
}

#define LDMATRIX_X4(r, addr) \
    asm volatile("ldmatrix.sync.aligned.m8n8.x4.shared.b16 {%0,%1,%2,%3}, [%4];" \
                 : "=r"((r)[0]), "=r"((r)[1]), "=r"((r)[2]), "=r"((r)[3]) \
                 : "r"(addr))

#define MMA_BF16(c, a, b0, b1) \
    asm volatile( \
        "mma.sync.aligned.m16n8k16.row.col.f32.bf16.bf16.f32 " \
        "{%0,%1,%2,%3}, {%4,%5,%6,%7}, {%8,%9}, {%0,%1,%2,%3};" \
        : "+f"((c)[0]), "+f"((c)[1]), "+f"((c)[2]), "+f"((c)[3]) \
        : "r"((a)[0]), "r"((a)[1]), "r"((a)[2]), "r"((a)[3]), \
          "r"(b0), "r"(b1))

// ldmatrix x4 address for a 16x16 bf16 tile in a [rows][32] bf16 buffer
// (64B rows, swizzle kg ^= (row>>1)&3). lane 0-15 -> rows, lane>>4 -> k half.
__device__ __forceinline__ uint32_t lm_addr(uint32_t buf, int rowbase, int ks,
                                            int lane) {
    int row = rowbase + (lane & 15);
    int kg = ks * 2 + (lane >> 4);
    return buf + row * 64 + (((kg ^ ((row >> 1) & 3))) << 4);
}

// ---------------------------------------------------------------------------
// CSR construction (unchanged from R5)
// ---------------------------------------------------------------------------

__global__ void k_init_deg(int n) {
    int i = blockIdx.x * blockDim.x + threadIdx.x;
    if (i < n) g_deg[i] = 1;
}

__global__ void k_count(const int* __restrict__ dst, int e) {
    int i = blockIdx.x * blockDim.x + threadIdx.x;
    if (i < e) atomicAdd(&g_deg[dst[i]], 1);
}

__global__ void k_scan1(int n) {
    __shared__ int s[1024];
    int gid = blockIdx.x * 1024 + threadIdx.x;
    int v = (gid < n) ? g_deg[gid] : 0;
    s[threadIdx.x] = v;
    __syncthreads();
    for (int off = 1; off < 1024; off <<= 1) {
        int t = (threadIdx.x >= off) ? s[threadIdx.x - off] : 0;
        __syncthreads();
        s[threadIdx.x] += t;
        __syncthreads();
    }
    if (gid < n) g_rowstart[gid] = s[threadIdx.x] - v;
    if (threadIdx.x == 1023) g_bsums[blockIdx.x] = s[1023];
}

__global__ void k_scanfill(int n, int nb) {
    __shared__ int soff;
    int gid = blockIdx.x * 1024 + threadIdx.x;
    if (threadIdx.x == 0) {
        int o = 0;
        for (int b = 0; b < (int)blockIdx.x; b++) o += g_bsums[b];
        soff = o;
    }
    __syncthreads();
    if (gid < n) {
        int rs = g_rowstart[gid] + soff;
        g_rowstart[gid] = rs;
        float d = rsqrtf((float)g_deg[gid]);
        g_dinv[gid] = d;
        g_col[rs] = gid;
        g_wgt[rs] = d * d;
        g_fill[gid] = 1;
    }
    if (gid == 0) {
        int o = 0;
        for (int b = 0; b < nb; b++) o += g_bsums[b];
        g_rowstart[n] = o;
    }
}

__global__ void k_fill_edges(const int* __restrict__ src,
                             const int* __restrict__ dst, int e) {
    int i = blockIdx.x * blockDim.x + threadIdx.x;
    if (i < e) {
        int s = src[i];
        int d = dst[i];
        int p = g_rowstart[d] + atomicAdd(&g_fill[d], 1);
        g_col[p] = s;
        g_wgt[p] = g_dinv[s] * g_dinv[d];
    }
}

// ---------------------------------------------------------------------------
// W pre-split: W [K,N] fp32 -> transposed K-major bf16 hi/lo [N][K]
// ---------------------------------------------------------------------------

template <int K, int N, int WSEL>
__global__ void k_wcvt(const float* __restrict__ W) {
    __nv_bfloat16* wh = (WSEL == 1) ? g_w1h : g_w2h;
    __nv_bfloat16* wl = (WSEL == 1) ? g_w1l : g_w2l;
    int idx = blockIdx.x * blockDim.x + threadIdx.x;
    if (idx < N * K) {
        int n = idx / K, k = idx % K;
        float v = W[k * N + n];
        __nv_bfloat16 h = __float2bfloat16(v);
        wh[idx] = h;
        wl[idx] = __float2bfloat16(v - __bfloat162float(h));
    }
}

// ---------------------------------------------------------------------------
// HMMA GEMM: C[M,N_] = A[M,K_] @ W  (W pre-split bf16 [N_][K_] K-major).
// BM=128/CTA, KC=32 chunks, 8 warps as 4(m)x2(n). 3 accumulating terms.
// WSEL=1: A=param x, C=g_hb (bf16). WSEL=2: A=g_a, C=g_h (fp32).
// ---------------------------------------------------------------------------

template <int N_, int K_, int WSEL>
__global__ void __launch_bounds__(256) k_hgemm(const float* __restrict__ Ain,
                                               int M) {
    constexpr int NCHUNK = K_ / 32;
    constexpr int NT16 = N_ / 32;        // 16-wide n tiles per warp
    constexpr int OFF_AL = 8192;         // A buffers: 128 rows x 64B
    constexpr int OFF_BH = 16384;
    constexpr int OFF_BL = 16384 + N_ * 64;

    __shared__ __align__(128) char smem[16384 + 2 * N_ * 64];

    const float* __restrict__ A = (WSEL == 2) ? (const float*)g_a : Ain;
    const __nv_bfloat16* __restrict__ Bh = (WSEL == 1) ? g_w1h : g_w2h;
    const __nv_bfloat16* __restrict__ Bl = (WSEL == 1) ? g_w1l : g_w2l;

    const uint32_t sb = smem_u32(smem);
    const int tid = threadIdx.x;
    const int wid = tid >> 5, lane = tid & 31;
    const int wm = wid & 3, wn = wid >> 2;   // 4 x 2 warp grid
    const int m0 = blockIdx.x * 128;

    float acc[2][N_ / 16][4];
#pragma unroll
    for (int i = 0; i < 2; i++)
#pragma unroll
        for (int j = 0; j < N_ / 16; j++)
#pragma unroll
            for (int q = 0; q < 4; q++) acc[i][j][q] = 0.f;

    for (int chunk = 0; chunk < NCHUNK; chunk++) {
        const int k0 = chunk * 32;
        // ---- stage A: fp32 -> bf16 hi/lo, swizzled 64B rows ----
#pragma unroll
        for (int i = 0; i < 4; i++) {
            int idx = tid + i * 256;           // 0..1023
            int row = idx >> 3, f4 = idx & 7;  // f4: float4 index (k = 4*f4)
            int gr = m0 + row;
            float4 v = make_float4(0.f, 0.f, 0.f, 0.f);
            if (gr < M) v = *(const float4*)(A + (size_t)gr * K_ + k0 + f4 * 4);
            __nv_bfloat16 h0 = __float2bfloat16(v.x);
            __nv_bfloat16 h1 = __float2bfloat16(v.y);
            __nv_bfloat16 h2 = __float2bfloat16(v.z);
            __nv_bfloat16 h3 = __float2bfloat16(v.w);
            __nv_bfloat162 hp0 = __halves2bfloat162(h0, h1);
            __nv_bfloat162 hp1 = __halves2bfloat162(h2, h3);
            __nv_bfloat162 lp0 = __floats2bfloat162_rn(
                v.x - __bfloat162float(h0), v.y - __bfloat162float(h1));
            __nv_bfloat162 lp1 = __floats2bfloat162_rn(
                v.z - __bfloat162float(h2), v.w - __bfloat162float(h3));
            int kg = f4 >> 1, half = f4 & 1;
            uint32_t byte = row * 64 + ((kg ^ ((row >> 1) & 3)) << 4) + half * 8;
            uint2 hu = make_uint2(*(uint32_t*)&hp0, *(uint32_t*)&hp1);
            uint2 lu = make_uint2(*(uint32_t*)&lp0, *(uint32_t*)&lp1);
            *(uint2*)(smem + byte) = hu;
            *(uint2*)(smem + OFF_AL + byte) = lu;
        }
        // ---- stage B: bf16 [N_][K_] -> swizzled 64B rows ----
#pragma unroll
        for (int i = 0; i < N_ * 4 / 256; i++) {
            int idx = tid + i * 256;
            int row = idx >> 2, kg = idx & 3;
            uint4 vh = *(const uint4*)(Bh + (size_t)row * K_ + k0 + kg * 8);
            uint4 vl = *(const uint4*)(Bl + (size_t)row * K_ + k0 + kg * 8);
            uint32_t byte = row * 64 + ((kg ^ ((row >> 1) & 3)) << 4);
            *(uint4*)(smem + OFF_BH + byte) = vh;
            *(uint4*)(smem + OFF_BL + byte) = vl;
        }
        __syncthreads();

        // ---- compute: 2 k-steps of 16 ----
#pragma unroll
        for (int ks = 0; ks < 2; ks++) {
            uint32_t ah[2][4], al[2][4];
#pragma unroll
            for (int mt = 0; mt < 2; mt++) {
                uint32_t ad = lm_addr(sb, wm * 32 + mt * 16, ks, lane);
                LDMATRIX_X4(ah[mt], ad);
                LDMATRIX_X4(al[mt], ad + OFF_AL);
            }
#pragma unroll
            for (int nt = 0; nt < NT16; nt++) {
                uint32_t bh[4], bl[4];
                uint32_t bd =
                    lm_addr(sb + OFF_BH, wn * (N_ / 2) + nt * 16, ks, lane);
                LDMATRIX_X4(bh, bd);
                LDMATRIX_X4(bl, bd + N_ * 64);
#pragma unroll
                for (int mt = 0; mt < 2; mt++) {
                    float* c0 = acc[mt][nt * 2 + 0];
                    float* c1 = acc[mt][nt * 2 + 1];
                    MMA_BF16(c0, ah[mt], bh[0], bh[2]);
                    MMA_BF16(c1, ah[mt], bh[1], bh[3]);
                    MMA_BF16(c0, al[mt], bh[0], bh[2]);
                    MMA_BF16(c1, al[mt], bh[1], bh[3]);
                    MMA_BF16(c0, ah[mt], bl[0], bl[2]);
                    MMA_BF16(c1, ah[mt], bl[1], bl[3]);
                }
            }
        }
        __syncthreads();
    }

    // ---- epilogue ----
#pragma unroll
    for (int mt = 0; mt < 2; mt++) {
#pragma unroll
        for (int nt8 = 0; nt8 < N_ / 16; nt8++) {
            const float* c = acc[mt][nt8];
            int row0 = m0 + wm * 32 + mt * 16 + (lane >> 2);
            int col = wn * (N_ / 2) + nt8 * 8 + 2 * (lane & 3);
            if (WSEL == 1) {
                __nv_bfloat162 p0 = __floats2bfloat162_rn(c[0], c[1]);
                __nv_bfloat162 p1 = __floats2bfloat162_rn(c[2], c[3]);
                if (row0 < M)
                    *(uint32_t*)(g_hb + (size_t)row0 * 128 + col) = *(uint32_t*)&p0;
                if (row0 + 8 < M)
                    *(uint32_t*)(g_hb + (size_t)(row0 + 8) * 128 + col) =
                        *(uint32_t*)&p1;
            } else {
                if (row0 < M)
                    *(float2*)(g_h + (size_t)row0 * N_ + col) =
                        make_float2(c[0], c[1]);
                if (row0 + 8 < M)
                    *(float2*)(g_h + (size_t)(row0 + 8) * N_ + col) =
                        make_float2(c[2], c[3]);
            }
        }
    }
}

// ---------------------------------------------------------------------------
// SpMM kernels (unchanged from R5)
// ---------------------------------------------------------------------------

__launch_bounds__(256)
__global__ void k_spmm1(const float* __restrict__ bias, int n) {
    int w = (blockIdx.x * 256 + threadIdx.x) >> 5;
    int lane = threadIdx.x & 31;
    if (w >= n) return;
    int beg = g_rowstart[w], end = g_rowstart[w + 1];

    float4 acc = make_float4(0.f, 0.f, 0.f, 0.f);
    const __nv_bfloat16* hb = g_hb + lane * 4;
    for (int e = beg; e < end; e++) {
        int s = g_col[e];
        float wt = g_wgt[e];
        uint2 raw = *(const uint2*)(hb + (size_t)s * 128);
        __nv_bfloat162 v01 = *reinterpret_cast<__nv_bfloat162*>(&raw.x);
        __nv_bfloat162 v23 = *reinterpret_cast<__nv_bfloat162*>(&raw.y);
        float2 f01 = __bfloat1622float2(v01);
        float2 f23 = __bfloat1622float2(v23);
        acc.x += wt * f01.x; acc.y += wt * f01.y;
        acc.z += wt * f23.x; acc.w += wt * f23.y;
    }
    float4 b = *(const float4*)(bias + lane * 4);
    acc.x = fmaxf(acc.x + b.x, 0.f);
    acc.y = fmaxf(acc.y + b.y, 0.f);
    acc.z = fmaxf(acc.z + b.z, 0.f);
    acc.w = fmaxf(acc.w + b.w, 0.f);
    *(float4*)(g_a + (size_t)w * 128 + lane * 4) = acc;
}

__launch_bounds__(256)
__global__ void k_spmm2(const float* __restrict__ bias, float* __restrict__ out,
                        int n) {
    int w = (blockIdx.x * 256 + threadIdx.x) >> 5;
    int lane = threadIdx.x & 31;
    if (w >= n) return;
    int beg = g_rowstart[w], end = g_rowstart[w + 1];

    float2 acc = make_float2(0.f, 0.f);
    const float* hb = g_h + lane * 2;
    for (int e = beg; e < end; e++) {
        int s = g_col[e];
        float wt = g_wgt[e];
        float2 v = *(const float2*)(hb + (size_t)s * 64);
        acc.x += wt * v.x; acc.y += wt * v.y;
    }
    float2 b = *(const float2*)(bias + lane * 2);
    acc.x += b.x; acc.y += b.y;
    *(float2*)(out + (size_t)w * 64 + lane * 2) = acc;
}

// ---------------------------------------------------------------------------

extern "C" void kernel_launch(void* const* d_in, const int* in_sizes, int n_in,
                              void* d_out, int out_size) {
    const float* x = (const float*)d_in[0];
    const int* ei = (const int*)d_in[1];      // int32
    const float* W1 = (const float*)d_in[2];
    const float* b1 = (const float*)d_in[3];
    const float* W2 = (const float*)d_in[4];
    const float* b2 = (const float*)d_in[5];
    float* out = (float*)d_out;

    const int N = in_sizes[0] / 256;   // 100000
    const int E = in_sizes[1] / 2;     // 1600000
    const int* src = ei;
    const int* dst = ei + E;
    const int NB = (N + 1023) / 1024;

    // #1..#3
    k_wcvt<256, 128, 1><<<(128 * 256 + 255) / 256, 256>>>(W1);
    k_init_deg<<<(N + 255) / 256, 256>>>(N);
    k_count<<<(E + 255) / 256, 256>>>(dst, E);

    // #4: GEMM1 (HMMA) — ncu capture lands here
    k_hgemm<128, 256, 1><<<(N + 127) / 128, 256>>>(x, N);

    // #5..#7: CSR
    k_scan1<<<NB, 1024>>>(N);
    k_scanfill<<<NB, 1024>>>(N, NB);
    k_fill_edges<<<(E + 255) / 256, 256>>>(src, dst, E);

    // #8: a1 = relu(Ahat h1 + b1)
    k_spmm1<<<((N * 32) + 255) / 256, 256>>>(b1, N);

    // #9..#10: GEMM2 (HMMA)
    k_wcvt<128, 64, 2><<<(64 * 128 + 255) / 256, 256>>>(W2);
    k_hgemm<64, 128, 2><<<(N + 127) / 128, 256>>>(nullptr, N);

    // #11: out = Ahat h2 + b2
    k_spmm2<<<((N * 32) + 255) / 256, 256>>>(b2, out, N);
}

// round 8
// speedup vs baseline: 1.5381x; 1.1350x over previous
#include <cuda_runtime.h>
#include <cuda_bf16.h>
#include <cstdint>
#include <cstddef>

// ---------------------------------------------------------------------------
// GCN 2-layer forward on GB300 — HMMA (mma.sync bf16) GEMMs + gather SpMM.
//   h1 = x @ W1    (3-term bf16 split, bf16-stored)
//   a1 = relu( Ahat @ h1 + b1 )
//   h2 = a1 @ W2   (3-term bf16 split, fp32-stored)
//   out = Ahat @ h2 + b2
// R8: register double-buffered chunk loads in k_hgemm — LDGs for chunk i+1
// issue before the MMA phase of chunk i, hiding global latency under tensor.
// ---------------------------------------------------------------------------

#define NNODES 100000
#define NEDGES 1600000
#define NNZ    (NNODES + NEDGES)

__device__ int   g_deg[NNODES];
__device__ int   g_fill[NNODES];
__device__ int   g_rowstart[NNODES + 1];
__device__ int   g_bsums[256];
__device__ float g_dinv[NNODES];
__device__ int   g_col[NNZ];
__device__ float g_wgt[NNZ];
__device__ __nv_bfloat16 g_hb[(size_t)NNODES * 128];  // h1 (bf16)
__device__ float g_h[(size_t)NNODES * 64];            // h2 (fp32)
__device__ float g_a[(size_t)NNODES * 128];           // a1
// W split (transposed, K-major rows): [N][K] bf16 hi/lo
__device__ __nv_bfloat16 g_w1h[128 * 256];
__device__ __nv_bfloat16 g_w1l[128 * 256];
__device__ __nv_bfloat16 g_w2h[64 * 128];
__device__ __nv_bfloat16 g_w2l[64 * 128];

// ------------------------------ helpers ------------------------------------

__device__ __forceinline__ uint32_t smem_u32(const void* p) {
    uint32_t a;
    asm("{ .reg .u64 t; cvta.to.shared.u64 t, %1; cvt.u32.u64 %0, t; }"
        : "=r"(a) : "l"(p));
    return a;
}

#define LDMATRIX_X4(r, addr) \
    asm volatile("ldmatrix.sync.aligned.m8n8.x4.shared.b16 {%0,%1,%2,%3}, [%4];" \
                 : "=r"((r)[0]), "=r"((r)[1]), "=r"((r)[2]), "=r"((r)[3]) \
                 : "r"(addr))

#define MMA_BF16(c, a, b0, b1) \
    asm volatile( \
        "mma.sync.aligned.m16n8k16.row.col.f32.bf16.bf16.f32 " \
        "{%0,%1,%2,%3}, {%4,%5,%6,%7}, {%8,%9}, {%0,%1,%2,%3};" \
        : "+f"((c)[0]), "+f"((c)[1]), "+f"((c)[2]), "+f"((c)[3]) \
        : "r"((a)[0]), "r"((a)[1]), "r"((a)[2]), "r"((a)[3]), \
          "r"(b0), "r"(b1))

// ldmatrix x4 address for a 16x16 bf16 tile in a [rows][32] bf16 buffer
// (64B rows, swizzle kg ^= (row>>1)&3). lane 0-15 -> rows, lane>>4 -> k half.
__device__ __forceinline__ uint32_t lm_addr(uint32_t buf, int rowbase, int ks,
                                            int lane) {
    int row = rowbase + (lane & 15);
    int kg = ks * 2 + (lane >> 4);
    return buf + row * 64 + (((kg ^ ((row >> 1) & 3))) << 4);
}

// ---------------------------------------------------------------------------
// CSR construction
// ---------------------------------------------------------------------------

__global__ void k_init_deg(int n) {
    int i = blockIdx.x * blockDim.x + threadIdx.x;
    if (i < n) g_deg[i] = 1;
}

__global__ void k_count(const int* __restrict__ dst, int e) {
    int i = blockIdx.x * blockDim.x + threadIdx.x;
    if (i < e) atomicAdd(&g_deg[dst[i]], 1);
}

__global__ void k_scan1(int n) {
    __shared__ int s[1024];
    int gid = blockIdx.x * 1024 + threadIdx.x;
    int v = (gid < n) ? g_deg[gid] : 0;
    s[threadIdx.x] = v;
    __syncthreads();
    for (int off = 1; off < 1024; off <<= 1) {
        int t = (threadIdx.x >= off) ? s[threadIdx.x - off] : 0;
        __syncthreads();
        s[threadIdx.x] += t;
        __syncthreads();
    }
    if (gid < n) g_rowstart[gid] = s[threadIdx.x] - v;
    if (threadIdx.x == 1023) g_bsums[blockIdx.x] = s[1023];
}

__global__ void k_scanfill(int n, int nb) {
    __shared__ int soff;
    int gid = blockIdx.x * 1024 + threadIdx.x;
    if (threadIdx.x == 0) {
        int o = 0;
        for (int b = 0; b < (int)blockIdx.x; b++) o += g_bsums[b];
        soff = o;
    }
    __syncthreads();
    if (gid < n) {
        int rs = g_rowstart[gid] + soff;
        g_rowstart[gid] = rs;
        float d = rsqrtf((float)g_deg[gid]);
        g_dinv[gid] = d;
        g_col[rs] = gid;
        g_wgt[rs] = d * d;
        g_fill[gid] = 1;
    }
    if (gid == 0) {
        int o = 0;
        for (int b = 0; b < nb; b++) o += g_bsums[b];
        g_rowstart[n] = o;
    }
}

__global__ void k_fill_edges(const int* __restrict__ src,
                             const int* __restrict__ dst, int e) {
    int i = blockIdx.x * blockDim.x + threadIdx.x;
    if (i < e) {
        int s = src[i];
        int d = dst[i];
        int p = g_rowstart[d] + atomicAdd(&g_fill[d], 1);
        g_col[p] = s;
        g_wgt[p] = g_dinv[s] * g_dinv[d];
    }
}

// ---------------------------------------------------------------------------
// W pre-split: W [K,N] fp32 -> transposed K-major bf16 hi/lo [N][K]
// ---------------------------------------------------------------------------

template <int K, int N, int WSEL>
__global__ void k_wcvt(const float* __restrict__ W) {
    __nv_bfloat16* wh = (WSEL == 1) ? g_w1h : g_w2h;
    __nv_bfloat16* wl = (WSEL == 1) ? g_w1l : g_w2l;
    int idx = blockIdx.x * blockDim.x + threadIdx.x;
    if (idx < N * K) {
        int n = idx / K, k = idx % K;
        float v = W[k * N + n];
        __nv_bfloat16 h = __float2bfloat16(v);
        wh[idx] = h;
        wl[idx] = __float2bfloat16(v - __bfloat162float(h));
    }
}

// ---------------------------------------------------------------------------
// HMMA GEMM with register double-buffered chunk loads.
// C[M,N_] = A[M,K_] @ W  (W pre-split bf16 [N_][K_] K-major).
// BM=128/CTA, KC=32 chunks, 8 warps as 4(m)x2(n). 3 accumulating terms.
// WSEL=1: A=param x, C=g_hb (bf16). WSEL=2: A=g_a, C=g_h (fp32).
// ---------------------------------------------------------------------------

template <int N_, int K_, int WSEL>
__global__ void __launch_bounds__(256) k_hgemm(const float* __restrict__ Ain,
                                               int M) {
    constexpr int NCHUNK = K_ / 32;
    constexpr int NT16 = N_ / 32;        // 16-wide n tiles per warp
    constexpr int NBQ = N_ * 4 / 256;    // B stage iterations (2 or 1)
    constexpr int OFF_AL = 8192;         // A buffers: 128 rows x 64B
    constexpr int OFF_BH = 16384;
    constexpr int OFF_BL = 16384 + N_ * 64;

    __shared__ __align__(128) char smem[16384 + 2 * N_ * 64];

    const float* __restrict__ A = (WSEL == 2) ? (const float*)g_a : Ain;
    const __nv_bfloat16* __restrict__ Bh = (WSEL == 1) ? g_w1h : g_w2h;
    const __nv_bfloat16* __restrict__ Bl = (WSEL == 1) ? g_w1l : g_w2l;

    const uint32_t sb = smem_u32(smem);
    const int tid = threadIdx.x;
    const int wid = tid >> 5, lane = tid & 31;
    const int wm = wid & 3, wn = wid >> 2;   // 4 x 2 warp grid
    const int m0 = blockIdx.x * 128;

    float acc[2][N_ / 16][4];
#pragma unroll
    for (int i = 0; i < 2; i++)
#pragma unroll
        for (int j = 0; j < N_ / 16; j++)
#pragma unroll
            for (int q = 0; q < 4; q++) acc[i][j][q] = 0.f;

    // per-thread stage coordinates (fixed across chunks)
    const int a_row[4] = {tid >> 3, (tid + 256) >> 3, (tid + 512) >> 3,
                          (tid + 768) >> 3};
    const int a_f4 = tid & 7;               // same low bits for all 4

    // ---- prefetch chunk 0 into registers ----
    float4 pa[4];
    uint4 pbh[NBQ], pbl[NBQ];
    {
        const int k0 = 0;
#pragma unroll
        for (int i = 0; i < 4; i++) {
            int gr = m0 + a_row[i];
            pa[i] = make_float4(0.f, 0.f, 0.f, 0.f);
            if (gr < M) pa[i] = *(const float4*)(A + (size_t)gr * K_ + k0 + a_f4 * 4);
        }
#pragma unroll
        for (int i = 0; i < NBQ; i++) {
            int idx = tid + i * 256;
            int row = idx >> 2, kg = idx & 3;
            pbh[i] = *(const uint4*)(Bh + (size_t)row * K_ + k0 + kg * 8);
            pbl[i] = *(const uint4*)(Bl + (size_t)row * K_ + k0 + kg * 8);
        }
    }

    for (int chunk = 0; chunk < NCHUNK; chunk++) {
        // ---- store prefetched chunk to smem (A: fp32 -> bf16 hi/lo) ----
#pragma unroll
        for (int i = 0; i < 4; i++) {
            float4 v = pa[i];
            int row = a_row[i];
            __nv_bfloat16 h0 = __float2bfloat16(v.x);
            __nv_bfloat16 h1 = __float2bfloat16(v.y);
            __nv_bfloat16 h2 = __float2bfloat16(v.z);
            __nv_bfloat16 h3 = __float2bfloat16(v.w);
            __nv_bfloat162 hp0 = __halves2bfloat162(h0, h1);
            __nv_bfloat162 hp1 = __halves2bfloat162(h2, h3);
            __nv_bfloat162 lp0 = __floats2bfloat162_rn(
                v.x - __bfloat162float(h0), v.y - __bfloat162float(h1));
            __nv_bfloat162 lp1 = __floats2bfloat162_rn(
                v.z - __bfloat162float(h2), v.w - __bfloat162float(h3));
            int kg = a_f4 >> 1, half = a_f4 & 1;
            uint32_t byte = row * 64 + ((kg ^ ((row >> 1) & 3)) << 4) + half * 8;
            *(uint2*)(smem + byte) =
                make_uint2(*(uint32_t*)&hp0, *(uint32_t*)&hp1);
            *(uint2*)(smem + OFF_AL + byte) =
                make_uint2(*(uint32_t*)&lp0, *(uint32_t*)&lp1);
        }
#pragma unroll
        for (int i = 0; i < NBQ; i++) {
            int idx = tid + i * 256;
            int row = idx >> 2, kg = idx & 3;
            uint32_t byte = row * 64 + ((kg ^ ((row >> 1) & 3)) << 4);
            *(uint4*)(smem + OFF_BH + byte) = pbh[i];
            *(uint4*)(smem + OFF_BL + byte) = pbl[i];
        }
        __syncthreads();

        // ---- issue LDGs for chunk+1 (latency hides under MMA below) ----
        if (chunk + 1 < NCHUNK) {
            const int k0 = (chunk + 1) * 32;
#pragma unroll
            for (int i = 0; i < 4; i++) {
                int gr = m0 + a_row[i];
                pa[i] = make_float4(0.f, 0.f, 0.f, 0.f);
                if (gr < M)
                    pa[i] = *(const float4*)(A + (size_t)gr * K_ + k0 + a_f4 * 4);
            }
#pragma unroll
            for (int i = 0; i < NBQ; i++) {
                int idx = tid + i * 256;
                int row = idx >> 2, kg = idx & 3;
                pbh[i] = *(const uint4*)(Bh + (size_t)row * K_ + k0 + kg * 8);
                pbl[i] = *(const uint4*)(Bl + (size_t)row * K_ + k0 + kg * 8);
            }
        }

        // ---- compute: 2 k-steps of 16 ----
#pragma unroll
        for (int ks = 0; ks < 2; ks++) {
            uint32_t ah[2][4], al[2][4];
#pragma unroll
            for (int mt = 0; mt < 2; mt++) {
                uint32_t ad = lm_addr(sb, wm * 32 + mt * 16, ks, lane);
                LDMATRIX_X4(ah[mt], ad);
                LDMATRIX_X4(al[mt], ad + OFF_AL);
            }
#pragma unroll
            for (int nt = 0; nt < NT16; nt++) {
                uint32_t bh[4], bl[4];
                uint32_t bd =
                    lm_addr(sb + OFF_BH, wn * (N_ / 2) + nt * 16, ks, lane);
                LDMATRIX_X4(bh, bd);
                LDMATRIX_X4(bl, bd + N_ * 64);
#pragma unroll
                for (int mt = 0; mt < 2; mt++) {
                    float* c0 = acc[mt][nt * 2 + 0];
                    float* c1 = acc[mt][nt * 2 + 1];
                    MMA_BF16(c0, ah[mt], bh[0], bh[2]);
                    MMA_BF16(c1, ah[mt], bh[1], bh[3]);
                    MMA_BF16(c0, al[mt], bh[0], bh[2]);
                    MMA_BF16(c1, al[mt], bh[1], bh[3]);
                    MMA_BF16(c0, ah[mt], bl[0], bl[2]);
                    MMA_BF16(c1, ah[mt], bl[1], bl[3]);
                }
            }
        }
        __syncthreads();
    }

    // ---- epilogue ----
#pragma unroll
    for (int mt = 0; mt < 2; mt++) {
#pragma unroll
        for (int nt8 = 0; nt8 < N_ / 16; nt8++) {
            const float* c = acc[mt][nt8];
            int row0 = m0 + wm * 32 + mt * 16 + (lane >> 2);
            int col = wn * (N_ / 2) + nt8 * 8 + 2 * (lane & 3);
            if (WSEL == 1) {
                __nv_bfloat162 p0 = __floats2bfloat162_rn(c[0], c[1]);
                __nv_bfloat162 p1 = __floats2bfloat162_rn(c[2], c[3]);
                if (row0 < M)
                    *(uint32_t*)(g_hb + (size_t)row0 * 128 + col) = *(uint32_t*)&p0;
                if (row0 + 8 < M)
                    *(uint32_t*)(g_hb + (size_t)(row0 + 8) * 128 + col) =
                        *(uint32_t*)&p1;
            } else {
                if (row0 < M)
                    *(float2*)(g_h + (size_t)row0 * N_ + col) =
                        make_float2(c[0], c[1]);
                if (row0 + 8 < M)
                    *(float2*)(g_h + (size_t)(row0 + 8) * N_ + col) =
                        make_float2(c[2], c[3]);
            }
        }
    }
}

// ---------------------------------------------------------------------------
// SpMM kernels
// ---------------------------------------------------------------------------

__launch_bounds__(256)
__global__ void k_spmm1(const float* __restrict__ bias, int n) {
    int w = (blockIdx.x * 256 + threadIdx.x) >> 5;
    int lane = threadIdx.x & 31;
    if (w >= n) return;
    int beg = g_rowstart[w], end = g_rowstart[w + 1];

    float4 acc = make_float4(0.f, 0.f, 0.f, 0.f);
    const __nv_bfloat16* hb = g_hb + lane * 4;
    for (int e = beg; e < end; e++) {
        int s = g_col[e];
        float wt = g_wgt[e];
        uint2 raw = *(const uint2*)(hb + (size_t)s * 128);
        __nv_bfloat162 v01 = *reinterpret_cast<__nv_bfloat162*>(&raw.x);
        __nv_bfloat162 v23 = *reinterpret_cast<__nv_bfloat162*>(&raw.y);
        float2 f01 = __bfloat1622float2(v01);
        float2 f23 = __bfloat1622float2(v23);
        acc.x += wt * f01.x; acc.y += wt * f01.y;
        acc.z += wt * f23.x; acc.w += wt * f23.y;
    }
    float4 b = *(const float4*)(bias + lane * 4);
    acc.x = fmaxf(acc.x + b.x, 0.f);
    acc.y = fmaxf(acc.y + b.y, 0.f);
    acc.z = fmaxf(acc.z + b.z, 0.f);
    acc.w = fmaxf(acc.w + b.w, 0.f);
    *(float4*)(g_a + (size_t)w * 128 + lane * 4) = acc;
}

__launch_bounds__(256)
__global__ void k_spmm2(const float* __restrict__ bias, float* __restrict__ out,
                        int n) {
    int w = (blockIdx.x * 256 + threadIdx.x) >> 5;
    int lane = threadIdx.x & 31;
    if (w >= n) return;
    int beg = g_rowstart[w], end = g_rowstart[w + 1];

    float2 acc = make_float2(0.f, 0.f);
    const float* hb = g_h + lane * 2;
    for (int e = beg; e < end; e++) {
        int s = g_col[e];
        float wt = g_wgt[e];
        float2 v = *(const float2*)(hb + (size_t)s * 64);
        acc.x += wt * v.x; acc.y += wt * v.y;
    }
    float2 b = *(const float2*)(bias + lane * 2);
    acc.x += b.x; acc.y += b.y;
    *(float2*)(out + (size_t)w * 64 + lane * 2) = acc;
}

// ---------------------------------------------------------------------------

extern "C" void kernel_launch(void* const* d_in, const int* in_sizes, int n_in,
                              void* d_out, int out_size) {
    const float* x = (const float*)d_in[0];
    const int* ei = (const int*)d_in[1];      // int32
    const float* W1 = (const float*)d_in[2];
    const float* b1 = (const float*)d_in[3];
    const float* W2 = (const float*)d_in[4];
    const float* b2 = (const float*)d_in[5];
    float* out = (float*)d_out;

    const int N = in_sizes[0] / 256;   // 100000
    const int E = in_sizes[1] / 2;     // 1600000
    const int* src = ei;
    const int* dst = ei + E;
    const int NB = (N + 1023) / 1024;

    // #1..#3
    k_wcvt<256, 128, 1><<<(128 * 256 + 255) / 256, 256>>>(W1);
    k_init_deg<<<(N + 255) / 256, 256>>>(N);
    k_count<<<(E + 255) / 256, 256>>>(dst, E);

    // #4: GEMM1 (HMMA, reg double-buffered) — ncu capture lands here
    k_hgemm<128, 256, 1><<<(N + 127) / 128, 256>>>(x, N);

    // #5..#7: CSR
    k_scan1<<<NB, 1024>>>(N);
    k_scanfill<<<NB, 1024>>>(N, NB);
    k_fill_edges<<<(E + 255) / 256, 256>>>(src, dst, E);

    // #8: a1 = relu(Ahat h1 + b1)
    k_spmm1<<<((N * 32) + 255) / 256, 256>>>(b1, N);

    // #9..#10: GEMM2 (HMMA)
    k_wcvt<128, 64, 2><<<(64 * 128 + 255) / 256, 256>>>(W2);
    k_hgemm<64, 128, 2><<<(N + 127) / 128, 256>>>(nullptr, N);

    // #11: out = Ahat h2 + b2
    k_spmm2<<<((N * 32) + 255) / 256, 256>>>(b2, out, N);
}

// round 9
// speedup vs baseline: 1.9509x; 1.2684x over previous
#include <cuda_runtime.h>
#include <cuda_fp16.h>
#include <cstdint>
#include <cstddef>

// ---------------------------------------------------------------------------
// GCN 2-layer forward on GB300 — fp16 HMMA GEMMs + gather SpMM.
//   h1 = x @ W1    (fp16 single-term mma, fp32 accum, fp16-stored)
//   a1 = relu( Ahat @ h1 + b1 )   (fp32)
//   h2 = a1 @ W2   (fp16 mma, fp16-stored)
//   out = Ahat @ h2 + b2          (fp32 out)
// fp16 (2^-11) everywhere replaces bf16+3-term split: 3x less tensor work,
// halved smem/regs -> 2 CTAs/SM, and halved SpMM2 gather traffic.
// ---------------------------------------------------------------------------

#define NNODES 100000
#define NEDGES 1600000
#define NNZ    (NNODES + NEDGES)

__device__ int   g_deg[NNODES];
__device__ int   g_fill[NNODES];
__device__ int   g_rowstart[NNODES + 1];
__device__ int   g_bsums[256];
__device__ float g_dinv[NNODES];
__device__ int   g_col[NNZ];
__device__ float g_wgt[NNZ];
__device__ __half g_h1[(size_t)NNODES * 128];   // h1 (fp16)
__device__ __half g_h2[(size_t)NNODES * 64];    // h2 (fp16)
__device__ float  g_a[(size_t)NNODES * 128];    // a1 (fp32)
// W transposed K-major [N][K], fp16
__device__ __half g_w1[128 * 256];
__device__ __half g_w2[64 * 128];

// ------------------------------ helpers ------------------------------------

__device__ __forceinline__ uint32_t smem_u32(const void* p) {
    uint32_t a;
    asm("{ .reg .u64 t; cvta.to.shared.u64 t, %1; cvt.u32.u64 %0, t; }"
        : "=r"(a) : "l"(p));
    return a;
}

#define LDMATRIX_X4(r, addr) \
    asm volatile("ldmatrix.sync.aligned.m8n8.x4.shared.b16 {%0,%1,%2,%3}, [%4];" \
                 : "=r"((r)[0]), "=r"((r)[1]), "=r"((r)[2]), "=r"((r)[3]) \
                 : "r"(addr))

#define MMA_F16(c, a, b0, b1) \
    asm volatile( \
        "mma.sync.aligned.m16n8k16.row.col.f32.f16.f16.f32 " \
        "{%0,%1,%2,%3}, {%4,%5,%6,%7}, {%8,%9}, {%0,%1,%2,%3};" \
        : "+f"((c)[0]), "+f"((c)[1]), "+f"((c)[2]), "+f"((c)[3]) \
        : "r"((a)[0]), "r"((a)[1]), "r"((a)[2]), "r"((a)[3]), \
          "r"(b0), "r"(b1))

// ldmatrix x4 address for a 16x16 fp16 tile in [rows][32] half buffer
// (64B rows, swizzle kg ^= (row>>1)&3). lanes 0-15 -> rows, lane>>4 -> k half.
__device__ __forceinline__ uint32_t lm_addr(uint32_t buf, int rowbase, int ks,
                                            int lane) {
    int row = rowbase + (lane & 15);
    int kg = ks * 2 + (lane >> 4);
    return buf + row * 64 + (((kg ^ ((row >> 1) & 3))) << 4);
}

// ---------------------------------------------------------------------------
// CSR construction (unchanged)
// ---------------------------------------------------------------------------

__global__ void k_init_deg(int n) {
    int i = blockIdx.x * blockDim.x + threadIdx.x;
    if (i < n) g_deg[i] = 1;
}

__global__ void k_count(const int* __restrict__ dst, int e) {
    int i = blockIdx.x * blockDim.x + threadIdx.x;
    if (i < e) atomicAdd(&g_deg[dst[i]], 1);
}

__global__ void k_scan1(int n) {
    __shared__ int s[1024];
    int gid = blockIdx.x * 1024 + threadIdx.x;
    int v = (gid < n) ? g_deg[gid] : 0;
    s[threadIdx.x] = v;
    __syncthreads();
    for (int off = 1; off < 1024; off <<= 1) {
        int t = (threadIdx.x >= off) ? s[threadIdx.x - off] : 0;
        __syncthreads();
        s[threadIdx.x] += t;
        __syncthreads();
    }
    if (gid < n) g_rowstart[gid] = s[threadIdx.x] - v;
    if (threadIdx.x == 1023) g_bsums[blockIdx.x] = s[1023];
}

__global__ void k_scanfill(int n, int nb) {
    __shared__ int soff;
    int gid = blockIdx.x * 1024 + threadIdx.x;
    if (threadIdx.x == 0) {
        int o = 0;
        for (int b = 0; b < (int)blockIdx.x; b++) o += g_bsums[b];
        soff = o;
    }
    __syncthreads();
    if (gid < n) {
        int rs = g_rowstart[gid] + soff;
        g_rowstart[gid] = rs;
        float d = rsqrtf((float)g_deg[gid]);
        g_dinv[gid] = d;
        g_col[rs] = gid;
        g_wgt[rs] = d * d;
        g_fill[gid] = 1;
    }
    if (gid == 0) {
        int o = 0;
        for (int b = 0; b < nb; b++) o += g_bsums[b];
        g_rowstart[n] = o;
    }
}

__global__ void k_fill_edges(const int* __restrict__ src,
                             const int* __restrict__ dst, int e) {
    int i = blockIdx.x * blockDim.x + threadIdx.x;
    if (i < e) {
        int s = src[i];
        int d = dst[i];
        int p = g_rowstart[d] + atomicAdd(&g_fill[d], 1);
        g_col[p] = s;
        g_wgt[p] = g_dinv[s] * g_dinv[d];
    }
}

// ---------------------------------------------------------------------------
// W convert: W [K,N] fp32 -> transposed K-major fp16 [N][K]
// ---------------------------------------------------------------------------

template <int K, int N, int WSEL>
__global__ void k_wcvt(const float* __restrict__ W) {
    __half* wo = (WSEL == 1) ? g_w1 : g_w2;
    int idx = blockIdx.x * blockDim.x + threadIdx.x;
    if (idx < N * K) {
        int n = idx / K, k = idx % K;
        wo[idx] = __float2half_rn(W[k * N + n]);
    }
}

// ---------------------------------------------------------------------------
// fp16 HMMA GEMM, register double-buffered chunk loads, 2 CTAs/SM.
// C[M,N_] = A[M,K_] @ W (fp16 [N_][K_] K-major). BM=128/CTA, KC=32 chunks,
// 8 warps as 4(m)x2(n). WSEL=1: A=x param, C=g_h1. WSEL=2: A=g_a, C=g_h2.
// ---------------------------------------------------------------------------

template <int N_, int K_, int WSEL>
__global__ void __launch_bounds__(256, 2) k_hgemm(const float* __restrict__ Ain,
                                                  int M) {
    constexpr int NCHUNK = K_ / 32;
    constexpr int NT16 = N_ / 32;        // 16-wide n tiles per warp
    constexpr int NBQ = N_ * 4 / 256;    // B stage iterations (2 or 1)
    constexpr int OFF_B = 8192;          // A: 128 rows x 64B = 8KB

    __shared__ __align__(128) char smem[8192 + N_ * 64];

    const float* __restrict__ A = (WSEL == 2) ? (const float*)g_a : Ain;
    const __half* __restrict__ Bw = (WSEL == 1) ? g_w1 : g_w2;

    const uint32_t sb = smem_u32(smem);
    const int tid = threadIdx.x;
    const int wid = tid >> 5, lane = tid & 31;
    const int wm = wid & 3, wn = wid >> 2;   // 4 x 2 warp grid
    const int m0 = blockIdx.x * 128;

    float acc[2][N_ / 16][4];
#pragma unroll
    for (int i = 0; i < 2; i++)
#pragma unroll
        for (int j = 0; j < N_ / 16; j++)
#pragma unroll
            for (int q = 0; q < 4; q++) acc[i][j][q] = 0.f;

    const int a_row[4] = {tid >> 3, (tid + 256) >> 3, (tid + 512) >> 3,
                          (tid + 768) >> 3};
    const int a_f4 = tid & 7;

    // ---- prefetch chunk 0 ----
    float4 pa[4];
    uint4 pb[NBQ];
    {
#pragma unroll
        for (int i = 0; i < 4; i++) {
            int gr = m0 + a_row[i];
            pa[i] = make_float4(0.f, 0.f, 0.f, 0.f);
            if (gr < M) pa[i] = *(const float4*)(A + (size_t)gr * K_ + a_f4 * 4);
        }
#pragma unroll
        for (int i = 0; i < NBQ; i++) {
            int idx = tid + i * 256;
            int row = idx >> 2, kg = idx & 3;
            pb[i] = *(const uint4*)(Bw + (size_t)row * K_ + kg * 8);
        }
    }

    for (int chunk = 0; chunk < NCHUNK; chunk++) {
        // ---- store prefetched chunk to smem (A: fp32 -> fp16) ----
#pragma unroll
        for (int i = 0; i < 4; i++) {
            float4 v = pa[i];
            int row = a_row[i];
            __half2 p0 = __floats2half2_rn(v.x, v.y);
            __half2 p1 = __floats2half2_rn(v.z, v.w);
            int kg = a_f4 >> 1, half = a_f4 & 1;
            uint32_t byte = row * 64 + ((kg ^ ((row >> 1) & 3)) << 4) + half * 8;
            *(uint2*)(smem + byte) = make_uint2(*(uint32_t*)&p0, *(uint32_t*)&p1);
        }
#pragma unroll
        for (int i = 0; i < NBQ; i++) {
            int idx = tid + i * 256;
            int row = idx >> 2, kg = idx & 3;
            uint32_t byte = row * 64 + ((kg ^ ((row >> 1) & 3)) << 4);
            *(uint4*)(smem + OFF_B + byte) = pb[i];
        }
        __syncthreads();

        // ---- issue LDGs for chunk+1 (hide under MMAs) ----
        if (chunk + 1 < NCHUNK) {
            const int k0 = (chunk + 1) * 32;
#pragma unroll
            for (int i = 0; i < 4; i++) {
                int gr = m0 + a_row[i];
                pa[i] = make_float4(0.f, 0.f, 0.f, 0.f);
                if (gr < M)
                    pa[i] = *(const float4*)(A + (size_t)gr * K_ + k0 + a_f4 * 4);
            }
#pragma unroll
            for (int i = 0; i < NBQ; i++) {
                int idx = tid + i * 256;
                int row = idx >> 2, kg = idx & 3;
                pb[i] = *(const uint4*)(Bw + (size_t)row * K_ + k0 + kg * 8);
            }
        }

        // ---- compute: 2 k-steps of 16 ----
#pragma unroll
        for (int ks = 0; ks < 2; ks++) {
            uint32_t am[2][4];
#pragma unroll
            for (int mt = 0; mt < 2; mt++) {
                uint32_t ad = lm_addr(sb, wm * 32 + mt * 16, ks, lane);
                LDMATRIX_X4(am[mt], ad);
            }
#pragma unroll
            for (int nt = 0; nt < NT16; nt++) {
                uint32_t bm[4];
                uint32_t bd =
                    lm_addr(sb + OFF_B, wn * (N_ / 2) + nt * 16, ks, lane);
                LDMATRIX_X4(bm, bd);
#pragma unroll
                for (int mt = 0; mt < 2; mt++) {
                    MMA_F16(acc[mt][nt * 2 + 0], am[mt], bm[0], bm[2]);
                    MMA_F16(acc[mt][nt * 2 + 1], am[mt], bm[1], bm[3]);
                }
            }
        }
        __syncthreads();
    }

    // ---- epilogue: fp16 store ----
    __half* C = (WSEL == 1) ? g_h1 : g_h2;
#pragma unroll
    for (int mt = 0; mt < 2; mt++) {
#pragma unroll
        for (int nt8 = 0; nt8 < N_ / 16; nt8++) {
            const float* c = acc[mt][nt8];
            int row0 = m0 + wm * 32 + mt * 16 + (lane >> 2);
            int col = wn * (N_ / 2) + nt8 * 8 + 2 * (lane & 3);
            __half2 p0 = __floats2half2_rn(c[0], c[1]);
            __half2 p1 = __floats2half2_rn(c[2], c[3]);
            if (row0 < M)
                *(uint32_t*)(C + (size_t)row0 * N_ + col) = *(uint32_t*)&p0;
            if (row0 + 8 < M)
                *(uint32_t*)(C + (size_t)(row0 + 8) * N_ + col) = *(uint32_t*)&p1;
        }
    }
}

// ---------------------------------------------------------------------------
// SpMM layer 1: a1 = relu(Ahat @ h1(fp16) + b1), F=128. warp/node, lane=4 feat.
// ---------------------------------------------------------------------------

__launch_bounds__(256)
__global__ void k_spmm1(const float* __restrict__ bias, int n) {
    int w = (blockIdx.x * 256 + threadIdx.x) >> 5;
    int lane = threadIdx.x & 31;
    if (w >= n) return;
    int beg = g_rowstart[w], end = g_rowstart[w + 1];

    float4 acc = make_float4(0.f, 0.f, 0.f, 0.f);
    const __half* hb = g_h1 + lane * 4;
    for (int e = beg; e < end; e++) {
        int s = g_col[e];
        float wt = g_wgt[e];
        uint2 raw = *(const uint2*)(hb + (size_t)s * 128);
        float2 f01 = __half22float2(*reinterpret_cast<__half2*>(&raw.x));
        float2 f23 = __half22float2(*reinterpret_cast<__half2*>(&raw.y));
        acc.x += wt * f01.x; acc.y += wt * f01.y;
        acc.z += wt * f23.x; acc.w += wt * f23.y;
    }
    float4 b = *(const float4*)(bias + lane * 4);
    acc.x = fmaxf(acc.x + b.x, 0.f);
    acc.y = fmaxf(acc.y + b.y, 0.f);
    acc.z = fmaxf(acc.z + b.z, 0.f);
    acc.w = fmaxf(acc.w + b.w, 0.f);
    *(float4*)(g_a + (size_t)w * 128 + lane * 4) = acc;
}

// ---------------------------------------------------------------------------
// SpMM layer 2: out = Ahat @ h2(fp16) + b2, F=64. lane covers 2 features.
// ---------------------------------------------------------------------------

__launch_bounds__(256)
__global__ void k_spmm2(const float* __restrict__ bias, float* __restrict__ out,
                        int n) {
    int w = (blockIdx.x * 256 + threadIdx.x) >> 5;
    int lane = threadIdx.x & 31;
    if (w >= n) return;
    int beg = g_rowstart[w], end = g_rowstart[w + 1];

    float2 acc = make_float2(0.f, 0.f);
    const __half* hb = g_h2 + lane * 2;
    for (int e = beg; e < end; e++) {
        int s = g_col[e];
        float wt = g_wgt[e];
        uint32_t raw = *(const uint32_t*)(hb + (size_t)s * 64);
        float2 v = __half22float2(*reinterpret_cast<__half2*>(&raw));
        acc.x += wt * v.x; acc.y += wt * v.y;
    }
    float2 b = *(const float2*)(bias + lane * 2);
    acc.x += b.x; acc.y += b.y;
    *(float2*)(out + (size_t)w * 64 + lane * 2) = acc;
}

// ---------------------------------------------------------------------------

extern "C" void kernel_launch(void* const* d_in, const int* in_sizes, int n_in,
                              void* d_out, int out_size) {
    const float* x = (const float*)d_in[0];
    const int* ei = (const int*)d_in[1];      // int32
    const float* W1 = (const float*)d_in[2];
    const float* b1 = (const float*)d_in[3];
    const float* W2 = (const float*)d_in[4];
    const float* b2 = (const float*)d_in[5];
    float* out = (float*)d_out;

    const int N = in_sizes[0] / 256;   // 100000
    const int E = in_sizes[1] / 2;     // 1600000
    const int* src = ei;
    const int* dst = ei + E;
    const int NB = (N + 1023) / 1024;

    // #1..#3
    k_wcvt<256, 128, 1><<<(128 * 256 + 255) / 256, 256>>>(W1);
    k_init_deg<<<(N + 255) / 256, 256>>>(N);
    k_count<<<(E + 255) / 256, 256>>>(dst, E);

    // #4: GEMM1 (fp16 HMMA) — ncu capture lands here
    k_hgemm<128, 256, 1><<<(N + 127) / 128, 256>>>(x, N);

    // #5..#7: CSR
    k_scan1<<<NB, 1024>>>(N);
    k_scanfill<<<NB, 1024>>>(N, NB);
    k_fill_edges<<<(E + 255) / 256, 256>>>(src, dst, E);

    // #8: a1 = relu(Ahat h1 + b1)
    k_spmm1<<<((N * 32) + 255) / 256, 256>>>(b1, N);

    // #9..#10: GEMM2 (fp16 HMMA)
    k_wcvt<128, 64, 2><<<(64 * 128 + 255) / 256, 256>>>(W2);
    k_hgemm<64, 128, 2><<<(N + 127) / 128, 256>>>(nullptr, N);

    // #11: out = Ahat h2 + b2
    k_spmm2<<<((N * 32) + 255) / 256, 256>>>(b2, out, N);
}